// round 3
// baseline (speedup 1.0000x reference)
#include <cuda_runtime.h>

#define N_NODES 100000
#define N_EDGES_MAX 1600000
#define IN_DIM  64
#define HID     32
#define CHUNK   1024
#define NB      ((N_NODES + CHUNK - 1) / CHUNK)   // 98

// Scratch: __device__ globals (no allocation allowed in kernel_launch)
__device__ __align__(128) float g_h[N_NODES * HID];   // (X W) * norm_src
__device__ int g_degout[N_NODES];
__device__ int g_degin[N_NODES];
__device__ int g_cursor[N_NODES];
__device__ int g_off[N_NODES];          // exclusive prefix sum of degin
__device__ int g_partial[NB];
__device__ int g_csr[N_EDGES_MAX];      // src ids grouped by dst

// ---------------------------------------------------------------------------
// 0) zero degree counters + cursors
// ---------------------------------------------------------------------------
__global__ void zero_kernel(int n) {
    int i = blockIdx.x * blockDim.x + threadIdx.x;
    if (i < n) { g_degout[i] = 0; g_degin[i] = 0; g_cursor[i] = 0; }
}

// ---------------------------------------------------------------------------
// 1) degrees (int4-vectorized index loads)
// ---------------------------------------------------------------------------
__global__ void deg_kernel(const int4* __restrict__ src4,
                           const int4* __restrict__ dst4,
                           const int* __restrict__ src,
                           const int* __restrict__ dst, int e) {
    int e4 = e >> 2;
    int i = blockIdx.x * blockDim.x + threadIdx.x;
    if (i < e4) {
        int4 s = src4[i];
        int4 d = dst4[i];
        atomicAdd(&g_degout[s.x], 1); atomicAdd(&g_degout[s.y], 1);
        atomicAdd(&g_degout[s.z], 1); atomicAdd(&g_degout[s.w], 1);
        atomicAdd(&g_degin[d.x], 1);  atomicAdd(&g_degin[d.y], 1);
        atomicAdd(&g_degin[d.z], 1);  atomicAdd(&g_degin[d.w], 1);
    }
    // tail
    if (i == 0) {
        for (int k = e4 * 4; k < e; k++) {
            atomicAdd(&g_degout[src[k]], 1);
            atomicAdd(&g_degin [dst[k]], 1);
        }
    }
}

// ---------------------------------------------------------------------------
// 2a) per-chunk partial sums of degin
// ---------------------------------------------------------------------------
__global__ void scan_partial_kernel(int n) {
    int b = blockIdx.x;
    int t = threadIdx.x;            // 256 threads, 4 elems each
    int i0 = b * CHUNK + t * 4;
    int s = 0;
#pragma unroll
    for (int j = 0; j < 4; j++)
        if (i0 + j < n) s += g_degin[i0 + j];
    // block reduce
    for (int o = 16; o; o >>= 1) s += __shfl_down_sync(~0u, s, o);
    __shared__ int red[8];
    if ((t & 31) == 0) red[t >> 5] = s;
    __syncthreads();
    if (t == 0) {
        int tot = 0;
#pragma unroll
        for (int w = 0; w < 8; w++) tot += red[w];
        g_partial[b] = tot;
    }
}

// ---------------------------------------------------------------------------
// 2b) final scan: block base = sum(partial[0..b)), then local exclusive scan
// ---------------------------------------------------------------------------
__global__ void scan_final_kernel(int n) {
    int b = blockIdx.x;
    int t = threadIdx.x;            // 256 threads
    __shared__ int s_base;
    __shared__ int red[8];
    __shared__ int warp_sums[8];

    // sum partial[0..b)  (NB <= 256)
    int v = (t < b && t < NB) ? g_partial[t] : 0;
    for (int o = 16; o; o >>= 1) v += __shfl_down_sync(~0u, v, o);
    if ((t & 31) == 0) red[t >> 5] = v;
    __syncthreads();
    if (t == 0) {
        int s = 0;
#pragma unroll
        for (int w = 0; w < 8; w++) s += red[w];
        s_base = s;
    }

    // local exclusive scan, 4 elems/thread
    int i0 = b * CHUNK + t * 4;
    int a0 = (i0 + 0 < n) ? g_degin[i0 + 0] : 0;
    int a1 = (i0 + 1 < n) ? g_degin[i0 + 1] : 0;
    int a2 = (i0 + 2 < n) ? g_degin[i0 + 2] : 0;
    int a3 = (i0 + 3 < n) ? g_degin[i0 + 3] : 0;
    int tsum = a0 + a1 + a2 + a3;
    int incl = tsum;
    int lane = t & 31;
    for (int o = 1; o < 32; o <<= 1) {
        int y = __shfl_up_sync(~0u, incl, o);
        if (lane >= o) incl += y;
    }
    int excl = incl - tsum;
    if (lane == 31) warp_sums[t >> 5] = incl;
    __syncthreads();
    int woff = 0;
    for (int w = 0; w < (t >> 5); w++) woff += warp_sums[w];
    int base = s_base + woff + excl;
    if (i0 + 0 < n) g_off[i0 + 0] = base;
    if (i0 + 1 < n) g_off[i0 + 1] = base + a0;
    if (i0 + 2 < n) g_off[i0 + 2] = base + a0 + a1;
    if (i0 + 3 < n) g_off[i0 + 3] = base + a0 + a1 + a2;
}

// ---------------------------------------------------------------------------
// 3) h = (X @ W) * norm_src.  32 rows/block, 256 threads, 4 cols/thread.
// ---------------------------------------------------------------------------
__global__ void gemm_kernel(const float4* __restrict__ X4,
                            const float4* __restrict__ W4, int n) {
    __shared__ float  xs[32 * 65];            // padded rows (65) vs bank conflicts
    __shared__ float4 Ws4[IN_DIM * (HID / 4)];  // 64 x 8 float4 = 8 KB

    int t = threadIdx.x;
    // stage W: 512 float4
#pragma unroll
    for (int i = t; i < IN_DIM * (HID / 4); i += 256)
        Ws4[i] = W4[i];

    int row0 = blockIdx.x * 32;
    // stage 32 rows of X: 32*64 floats = 512 float4, coalesced
#pragma unroll
    for (int i = t; i < 512; i += 256) {
        int r = i >> 4;               // float4 idx 16 per row
        int c = i & 15;
        if (row0 + r < n) {
            float4 v = X4[(row0 + r) * (IN_DIM / 4) + c];
            float* p = xs + r * 65 + c * 4;
            p[0] = v.x; p[1] = v.y; p[2] = v.z; p[3] = v.w;
        }
    }
    __syncthreads();

    int rl  = t >> 3;                 // row in block 0..31
    int c4  = t & 7;                  // col group 0..7
    int row = row0 + rl;
    if (row >= n) return;

    const float* xr = xs + rl * 65;
    float4 acc = make_float4(0.f, 0.f, 0.f, 0.f);
#pragma unroll
    for (int k = 0; k < IN_DIM; k++) {
        float  xv = xr[k];
        float4 w  = Ws4[k * 8 + c4];
        acc.x += xv * w.x;
        acc.y += xv * w.y;
        acc.z += xv * w.z;
        acc.w += xv * w.w;
    }

    float nrm = rsqrtf(fmaxf((float)g_degout[row], 1.f));
    acc.x *= nrm; acc.y *= nrm; acc.z *= nrm; acc.w *= nrm;
    *reinterpret_cast<float4*>(g_h + row * HID + c4 * 4) = acc;
}

// ---------------------------------------------------------------------------
// 4) fill CSR: for each edge, csr[off[dst] + cursor[dst]++] = src
// ---------------------------------------------------------------------------
__global__ void fill_kernel(const int4* __restrict__ src4,
                            const int4* __restrict__ dst4,
                            const int* __restrict__ src,
                            const int* __restrict__ dst, int e) {
    int e4 = e >> 2;
    int i = blockIdx.x * blockDim.x + threadIdx.x;
    if (i < e4) {
        int4 s = src4[i];
        int4 d = dst4[i];
        g_csr[g_off[d.x] + atomicAdd(&g_cursor[d.x], 1)] = s.x;
        g_csr[g_off[d.y] + atomicAdd(&g_cursor[d.y], 1)] = s.y;
        g_csr[g_off[d.z] + atomicAdd(&g_cursor[d.z], 1)] = s.z;
        g_csr[g_off[d.w] + atomicAdd(&g_cursor[d.w], 1)] = s.w;
    }
    if (i == 0) {
        for (int k = e4 * 4; k < e; k++)
            g_csr[g_off[dst[k]] + atomicAdd(&g_cursor[dst[k]], 1)] = src[k];
    }
}

// ---------------------------------------------------------------------------
// 5) aggregate + finalize: warp per dst node, lane = column.
//    out[d] = relu( (sum_{s in N(d)} h[s]) * norm_dst + b )
// ---------------------------------------------------------------------------
__global__ void agg_kernel(float* __restrict__ out,
                           const float* __restrict__ b, int n) {
    int warp = (blockIdx.x * blockDim.x + threadIdx.x) >> 5;
    int lane = threadIdx.x & 31;
    if (warp >= n) return;

    int start = g_off[warp];
    int deg   = g_degin[warp];

    float acc = 0.f;
    for (int kb = 0; kb < deg; kb += 32) {
        int rem = deg - kb;
        int cnt = rem < 32 ? rem : 32;
        int myidx = (lane < cnt) ? g_csr[start + kb + lane] : 0;
        int j = 0;
#pragma unroll 4
        for (; j + 4 <= cnt; j += 4) {
            int s0 = __shfl_sync(~0u, myidx, j + 0);
            int s1 = __shfl_sync(~0u, myidx, j + 1);
            int s2 = __shfl_sync(~0u, myidx, j + 2);
            int s3 = __shfl_sync(~0u, myidx, j + 3);
            float v0 = g_h[s0 * HID + lane];
            float v1 = g_h[s1 * HID + lane];
            float v2 = g_h[s2 * HID + lane];
            float v3 = g_h[s3 * HID + lane];
            acc += v0; acc += v1; acc += v2; acc += v3;
        }
        for (; j < cnt; j++) {
            int s = __shfl_sync(~0u, myidx, j);
            acc += g_h[s * HID + lane];
        }
    }

    float nrm = rsqrtf(fmaxf((float)deg, 1.f));
    out[warp * HID + lane] = fmaxf(acc * nrm + b[lane], 0.f);
}

// ---------------------------------------------------------------------------
extern "C" void kernel_launch(void* const* d_in, const int* in_sizes, int n_in,
                              void* d_out, int out_size) {
    const float* features = (const float*)d_in[0];   // [N, 64]
    const int*   src      = (const int*)  d_in[1];   // [E]
    const int*   dst      = (const int*)  d_in[2];   // [E]
    const float* W        = (const float*)d_in[3];   // [64, 32]
    const float* b        = (const float*)d_in[4];   // [32]
    float*       out      = (float*)d_out;           // [N, 32]

    int n = in_sizes[0] / IN_DIM;                    // 100000
    int e = in_sizes[1];                             // 1600000

    // 0) zero counters
    zero_kernel<<<(n + 255) / 256, 256>>>(n);

    // 1) degrees
    int e4 = e >> 2;
    deg_kernel<<<(e4 + 255) / 256, 256>>>((const int4*)src, (const int4*)dst,
                                          src, dst, e);

    // 2) exclusive scan of degin -> off
    scan_partial_kernel<<<NB, 256>>>(n);
    scan_final_kernel<<<NB, 256>>>(n);

    // 3) h = (X W) * norm_src
    gemm_kernel<<<(n + 31) / 32, 256>>>((const float4*)features,
                                        (const float4*)W, n);

    // 4) CSR fill
    fill_kernel<<<(e4 + 255) / 256, 256>>>((const int4*)src, (const int4*)dst,
                                           src, dst, e);

    // 5) aggregate + normalize + bias + relu  (warp per node)
    agg_kernel<<<(n * 32 + 255) / 256, 256>>>(out, b, n);
}

// round 4
// speedup vs baseline: 1.0273x; 1.0273x over previous
#include <cuda_runtime.h>
#include <cuda_fp16.h>

#define N_NODES 100000
#define IN_DIM  64
#define HID     32

// Scratch: __device__ globals (no allocation allowed in kernel_launch)
__device__ __align__(128) __half g_h[N_NODES * HID];  // (X W) * norm_src, fp16
__device__ float g_degout[N_NODES];
__device__ float g_degin[N_NODES];

// ---------------------------------------------------------------------------
// 1) degrees: int4-vectorized index loads, 4 edges per thread
// ---------------------------------------------------------------------------
__global__ void deg_kernel(const int4* __restrict__ src4,
                           const int4* __restrict__ dst4,
                           const int* __restrict__ src,
                           const int* __restrict__ dst, int e) {
    int e4 = e >> 2;
    int i = blockIdx.x * blockDim.x + threadIdx.x;
    if (i < e4) {
        int4 s = src4[i];
        int4 d = dst4[i];
        atomicAdd(&g_degout[s.x], 1.f); atomicAdd(&g_degout[s.y], 1.f);
        atomicAdd(&g_degout[s.z], 1.f); atomicAdd(&g_degout[s.w], 1.f);
        atomicAdd(&g_degin[d.x], 1.f);  atomicAdd(&g_degin[d.y], 1.f);
        atomicAdd(&g_degin[d.z], 1.f);  atomicAdd(&g_degin[d.w], 1.f);
    }
    if (i == 0) {   // tail (e % 4)
        for (int k = e4 * 4; k < e; k++) {
            atomicAdd(&g_degout[src[k]], 1.f);
            atomicAdd(&g_degin [dst[k]], 1.f);
        }
    }
}

// ---------------------------------------------------------------------------
// 2) h = (X @ W) * norm_src -> fp16.  8 rows/block; X + W staged in smem.
// ---------------------------------------------------------------------------
__global__ void gemm_kernel(const float4* __restrict__ X4,
                            const float* __restrict__ W, int n) {
    __shared__ float Ws[IN_DIM * HID];     // 8 KB
    __shared__ float4 xs4[8 * IN_DIM / 4]; // 2 KB

    for (int i = threadIdx.x; i < IN_DIM * HID; i += blockDim.x)
        Ws[i] = W[i];

    int row0 = blockIdx.x * 8;
    if (threadIdx.x < 128) {
        int idx = row0 * (IN_DIM / 4) + threadIdx.x;
        if (row0 + (threadIdx.x >> 4) < n)
            xs4[threadIdx.x] = X4[idx];
    }
    __syncthreads();

    int row = row0 + (threadIdx.x >> 5);
    int col = threadIdx.x & 31;
    if (row >= n) return;

    const float4* xr = xs4 + (threadIdx.x >> 5) * (IN_DIM / 4);
    float acc = 0.f;
#pragma unroll
    for (int k4 = 0; k4 < IN_DIM / 4; k4++) {
        float4 x = xr[k4];
        int k = k4 * 4;
        acc += x.x * Ws[(k + 0) * HID + col];
        acc += x.y * Ws[(k + 1) * HID + col];
        acc += x.z * Ws[(k + 2) * HID + col];
        acc += x.w * Ws[(k + 3) * HID + col];
    }

    float nrm = rsqrtf(fmaxf(g_degout[row], 1.f));
    g_h[row * HID + col] = __float2half(acc * nrm);
}

// ---------------------------------------------------------------------------
// 3) edge scatter: out[dst] += h[src].  512-edge tiles, smem-staged indices;
//    8 threads/edge, each gathers 4 halfs (8B), converts, red.add.v4.f32.
//    Traffic/edge: 64B fp16 gather + 128B fp32 RMW (was 128+128).
// ---------------------------------------------------------------------------
#define TILE 512
__global__ void scatter_kernel(const int* __restrict__ src,
                               const int* __restrict__ dst,
                               float* __restrict__ out, int e) {
    __shared__ int s_src[TILE];
    __shared__ int s_dst[TILE];

    int base = blockIdx.x * TILE;
    int tile_n = min(TILE, e - base);

    for (int i = threadIdx.x; i < tile_n; i += blockDim.x) {
        s_src[i] = src[base + i];
        s_dst[i] = dst[base + i];
    }
    __syncthreads();

    int sub = threadIdx.x >> 3;          // edge slot within pass (0..31)
    int c   = (threadIdx.x & 7) << 2;    // float col offset 0,4,...,28

#pragma unroll 4
    for (int k = 0; k < TILE; k += 32) {
        int el = k + sub;
        if (el >= tile_n) break;
        int s = s_src[el];               // broadcast LDS
        int d = s_dst[el];
        // gather 4 halfs = 8 bytes
        uint2 raw = *reinterpret_cast<const uint2*>(g_h + s * HID + c);
        __half2 h01 = *reinterpret_cast<__half2*>(&raw.x);
        __half2 h23 = *reinterpret_cast<__half2*>(&raw.y);
        float2 f01 = __half22float2(h01);
        float2 f23 = __half22float2(h23);
        float* p = out + d * HID + c;
        asm volatile("red.global.add.v4.f32 [%0], {%1,%2,%3,%4};"
                     :: "l"(p), "f"(f01.x), "f"(f01.y), "f"(f23.x), "f"(f23.y)
                     : "memory");
    }
}

// ---------------------------------------------------------------------------
// 4) out = relu(agg * norm_dst + b), in place, float4-vectorized
// ---------------------------------------------------------------------------
__global__ void fin_kernel(float4* __restrict__ out4,
                           const float* __restrict__ b, int n) {
    int i = blockIdx.x * blockDim.x + threadIdx.x;   // [0, n*8)
    if (i >= n * (HID / 4)) return;
    int row  = i >> 3;
    int col4 = (i & 7) << 2;
    float nrm = rsqrtf(fmaxf(g_degin[row], 1.f));
    float4 v = out4[i];
    v.x = fmaxf(v.x * nrm + b[col4 + 0], 0.f);
    v.y = fmaxf(v.y * nrm + b[col4 + 1], 0.f);
    v.z = fmaxf(v.z * nrm + b[col4 + 2], 0.f);
    v.w = fmaxf(v.w * nrm + b[col4 + 3], 0.f);
    out4[i] = v;
}

// ---------------------------------------------------------------------------
extern "C" void kernel_launch(void* const* d_in, const int* in_sizes, int n_in,
                              void* d_out, int out_size) {
    const float* features = (const float*)d_in[0];   // [N, 64]
    const int*   src      = (const int*)  d_in[1];   // [E]
    const int*   dst      = (const int*)  d_in[2];   // [E]
    const float* W        = (const float*)d_in[3];   // [64, 32]
    const float* b        = (const float*)d_in[4];   // [32]
    float*       out      = (float*)d_out;           // [N, 32]

    int n = in_sizes[0] / IN_DIM;                    // 100000
    int e = in_sizes[1];                             // 1600000

    // 0) zero accumulators via memset nodes (no kernel launch needed)
    void* p_degout = nullptr;
    void* p_degin  = nullptr;
    cudaGetSymbolAddress(&p_degout, g_degout);
    cudaGetSymbolAddress(&p_degin,  g_degin);
    cudaMemsetAsync(out, 0, (size_t)n * HID * sizeof(float), 0);
    cudaMemsetAsync(p_degout, 0, (size_t)n * sizeof(float), 0);
    cudaMemsetAsync(p_degin,  0, (size_t)n * sizeof(float), 0);

    // 1) degrees
    int e4 = e >> 2;
    deg_kernel<<<(e4 + 255) / 256, 256>>>((const int4*)src, (const int4*)dst,
                                          src, dst, e);

    // 2) h = (X W) * norm_src  (fp16 output)
    gemm_kernel<<<(n + 7) / 8, 256>>>((const float4*)features, W, n);

    // 3) scatter-add over edges
    scatter_kernel<<<(e + TILE - 1) / TILE, 256>>>(src, dst, out, e);

    // 4) finalize
    fin_kernel<<<(n * (HID / 4) + 255) / 256, 256>>>((float4*)out, b, n);
}

// round 8
// speedup vs baseline: 1.2804x; 1.2465x over previous
#include <cuda_runtime.h>
#include <cuda_fp16.h>

#define N_NODES 100000
#define IN_DIM  64
#define HID     32

// Scratch: __device__ globals (no allocation allowed in kernel_launch)
__device__ __align__(128) __half g_h[N_NODES * HID];  // (X W) * norm_src, fp16
__device__ float g_degout[N_NODES];
__device__ float g_degin[N_NODES];

// ---------------------------------------------------------------------------
// 1) degrees: int4-vectorized index loads, 4 edges per thread
// ---------------------------------------------------------------------------
__global__ void deg_kernel(const int4* __restrict__ src4,
                           const int4* __restrict__ dst4,
                           const int* __restrict__ src,
                           const int* __restrict__ dst, int e) {
    int e4 = e >> 2;
    int i = blockIdx.x * blockDim.x + threadIdx.x;
    if (i < e4) {
        int4 s = src4[i];
        int4 d = dst4[i];
        atomicAdd(&g_degout[s.x], 1.f); atomicAdd(&g_degout[s.y], 1.f);
        atomicAdd(&g_degout[s.z], 1.f); atomicAdd(&g_degout[s.w], 1.f);
        atomicAdd(&g_degin[d.x], 1.f);  atomicAdd(&g_degin[d.y], 1.f);
        atomicAdd(&g_degin[d.z], 1.f);  atomicAdd(&g_degin[d.w], 1.f);
    }
    if (i == 0) {   // tail (e % 4)
        for (int k = e4 * 4; k < e; k++) {
            atomicAdd(&g_degout[src[k]], 1.f);
            atomicAdd(&g_degin [dst[k]], 1.f);
        }
    }
}

// ---------------------------------------------------------------------------
// 2) h = (X @ W) * norm_src -> fp16.
//    64 rows/block. W column slice lives in REGISTERS (64/thread, loaded once
//    per warp, coalesced). X tile staged in smem, read as float4 broadcasts
//    (conflict-free). Per row: 16 LDS.128 + 64 FFMA -> FMA-pipe bound.
// ---------------------------------------------------------------------------
#define GEMM_ROWS 64
__global__ void __launch_bounds__(256, 2)
gemm_kernel(const float4* __restrict__ X4,
            const float* __restrict__ W, int n) {
    __shared__ float4 xs4[GEMM_ROWS * (IN_DIM / 4)];   // 64 rows x 16 float4 = 16KB

    int t    = threadIdx.x;
    int lane = t & 31;
    int warp = t >> 5;                  // 0..7
    int row0 = blockIdx.x * GEMM_ROWS;

    // W column slice into registers: w[k] = W[k][lane]  (coalesced LDG)
    float w[IN_DIM];
#pragma unroll
    for (int k = 0; k < IN_DIM; k++)
        w[k] = __ldg(W + k * HID + lane);

    // stage 64 rows of X: 1024 float4, 4 per thread, coalesced
#pragma unroll
    for (int i = t; i < GEMM_ROWS * (IN_DIM / 4); i += 256) {
        int r = i >> 4;
        if (row0 + r < n) xs4[i] = X4[row0 * (IN_DIM / 4) + i];
    }
    __syncthreads();

    // each warp handles 8 rows; lane = output column
#pragma unroll
    for (int rr = 0; rr < 8; rr++) {
        int rl  = warp * 8 + rr;
        int row = row0 + rl;
        if (row >= n) break;

        const float4* xr = xs4 + rl * (IN_DIM / 4);
        float acc = 0.f;
#pragma unroll
        for (int k4 = 0; k4 < IN_DIM / 4; k4++) {
            float4 x = xr[k4];          // broadcast LDS.128
            acc += x.x * w[k4 * 4 + 0];
            acc += x.y * w[k4 * 4 + 1];
            acc += x.z * w[k4 * 4 + 2];
            acc += x.w * w[k4 * 4 + 3];
        }

        float nrm = rsqrtf(fmaxf(g_degout[row], 1.f));
        g_h[row * HID + lane] = __float2half(acc * nrm);
    }
}

// ---------------------------------------------------------------------------
// 3) edge scatter: out[dst] += h[src].  512-edge tiles, smem-staged indices;
//    8 threads/edge, each gathers 4 halfs (8B), converts, red.add.v4.f32.
// ---------------------------------------------------------------------------
#define TILE 512
__global__ void scatter_kernel(const int* __restrict__ src,
                               const int* __restrict__ dst,
                               float* __restrict__ out, int e) {
    __shared__ int s_src[TILE];
    __shared__ int s_dst[TILE];

    int base = blockIdx.x * TILE;
    int tile_n = min(TILE, e - base);

    for (int i = threadIdx.x; i < tile_n; i += blockDim.x) {
        s_src[i] = src[base + i];
        s_dst[i] = dst[base + i];
    }
    __syncthreads();

    int sub = threadIdx.x >> 3;          // edge slot within pass (0..31)
    int c   = (threadIdx.x & 7) << 2;    // float col offset 0,4,...,28

#pragma unroll 4
    for (int k = 0; k < TILE; k += 32) {
        int el = k + sub;
        if (el >= tile_n) break;
        int s = s_src[el];               // broadcast LDS
        int d = s_dst[el];
        uint2 raw = *reinterpret_cast<const uint2*>(g_h + s * HID + c);
        __half2 h01 = *reinterpret_cast<__half2*>(&raw.x);
        __half2 h23 = *reinterpret_cast<__half2*>(&raw.y);
        float2 f01 = __half22float2(h01);
        float2 f23 = __half22float2(h23);
        float* p = out + d * HID + c;
        asm volatile("red.global.add.v4.f32 [%0], {%1,%2,%3,%4};"
                     :: "l"(p), "f"(f01.x), "f"(f01.y), "f"(f23.x), "f"(f23.y)
                     : "memory");
    }
}

// ---------------------------------------------------------------------------
// 4) out = relu(agg * norm_dst + b), in place, float4-vectorized
// ---------------------------------------------------------------------------
__global__ void fin_kernel(float4* __restrict__ out4,
                           const float* __restrict__ b, int n) {
    int i = blockIdx.x * blockDim.x + threadIdx.x;   // [0, n*8)
    if (i >= n * (HID / 4)) return;
    int row  = i >> 3;
    int col4 = (i & 7) << 2;
    float nrm = rsqrtf(fmaxf(g_degin[row], 1.f));
    float4 v = out4[i];
    v.x = fmaxf(v.x * nrm + b[col4 + 0], 0.f);
    v.y = fmaxf(v.y * nrm + b[col4 + 1], 0.f);
    v.z = fmaxf(v.z * nrm + b[col4 + 2], 0.f);
    v.w = fmaxf(v.w * nrm + b[col4 + 3], 0.f);
    out4[i] = v;
}

// ---------------------------------------------------------------------------
extern "C" void kernel_launch(void* const* d_in, const int* in_sizes, int n_in,
                              void* d_out, int out_size) {
    const float* features = (const float*)d_in[0];   // [N, 64]
    const int*   src      = (const int*)  d_in[1];   // [E]
    const int*   dst      = (const int*)  d_in[2];   // [E]
    const float* W        = (const float*)d_in[3];   // [64, 32]
    const float* b        = (const float*)d_in[4];   // [32]
    float*       out      = (float*)d_out;           // [N, 32]

    int n = in_sizes[0] / IN_DIM;                    // 100000
    int e = in_sizes[1];                             // 1600000

    // 0) zero accumulators via memset nodes
    void* p_degout = nullptr;
    void* p_degin  = nullptr;
    cudaGetSymbolAddress(&p_degout, g_degout);
    cudaGetSymbolAddress(&p_degin,  g_degin);
    cudaMemsetAsync(out, 0, (size_t)n * HID * sizeof(float), 0);
    cudaMemsetAsync(p_degout, 0, (size_t)n * sizeof(float), 0);
    cudaMemsetAsync(p_degin,  0, (size_t)n * sizeof(float), 0);

    // 1) degrees
    int e4 = e >> 2;
    deg_kernel<<<(e4 + 255) / 256, 256>>>((const int4*)src, (const int4*)dst,
                                          src, dst, e);

    // 2) h = (X W) * norm_src  (fp16 output, register-blocked W)
    gemm_kernel<<<(n + GEMM_ROWS - 1) / GEMM_ROWS, 256>>>(
        (const float4*)features, W, n);

    // 3) scatter-add over edges
    scatter_kernel<<<(e + TILE - 1) / TILE, 256>>>(src, dst, out, e);

    // 4) finalize
    fin_kernel<<<(n * (HID / 4) + 255) / 256, 256>>>((float4*)out, b, n);
}

// round 9
// speedup vs baseline: 1.3717x; 1.0712x over previous
#include <cuda_runtime.h>
#include <cuda_fp16.h>

#define N_NODES 100000
#define IN_DIM  64
#define HID     32

// Scratch: __device__ globals (no allocation allowed in kernel_launch)
__device__ __align__(128) __half g_h[N_NODES * HID];  // raw XW then normed, fp16
__device__ float g_degout[N_NODES];
__device__ float g_degin[N_NODES];

// ---------------------------------------------------------------------------
// 1) FUSED: even blocks do gemm_raw (FMA-bound), odd blocks do degree atomics
//    (LTS-bound). Independent work -> concurrent occupancy of both pipes.
// ---------------------------------------------------------------------------
#define GEMM_ROWS 64
// gemm blocks: ceil(100000/64) = 1563 ; deg blocks: ceil(400000/256) = 1563

__global__ void __launch_bounds__(256, 2)
fused_gemm_deg_kernel(const float4* __restrict__ X4,
                      const float* __restrict__ W,
                      const int4* __restrict__ src4,
                      const int4* __restrict__ dst4, int n, int e) {
    __shared__ float4 xs4[GEMM_ROWS * (IN_DIM / 4)];   // 16KB (gemm role only)

    int t = threadIdx.x;

    if (blockIdx.x & 1) {
        // ---- degree role ----
        int bid = blockIdx.x >> 1;
        int e4 = e >> 2;
        int i = bid * 256 + t;
        if (i < e4) {
            int4 s = src4[i];
            int4 d = dst4[i];
            atomicAdd(&g_degout[s.x], 1.f); atomicAdd(&g_degout[s.y], 1.f);
            atomicAdd(&g_degout[s.z], 1.f); atomicAdd(&g_degout[s.w], 1.f);
            atomicAdd(&g_degin[d.x], 1.f);  atomicAdd(&g_degin[d.y], 1.f);
            atomicAdd(&g_degin[d.z], 1.f);  atomicAdd(&g_degin[d.w], 1.f);
        }
        if (i == 0) {   // tail (e % 4)
            const int* src = (const int*)src4;
            const int* dst = (const int*)dst4;
            for (int k = e4 * 4; k < e; k++) {
                atomicAdd(&g_degout[src[k]], 1.f);
                atomicAdd(&g_degin [dst[k]], 1.f);
            }
        }
        return;
    }

    // ---- gemm role: h_raw = X @ W  -> fp16 (norm applied later) ----
    int bid  = blockIdx.x >> 1;
    int lane = t & 31;
    int warp = t >> 5;                  // 0..7
    int row0 = bid * GEMM_ROWS;

    float w[IN_DIM];
#pragma unroll
    for (int k = 0; k < IN_DIM; k++)
        w[k] = __ldg(W + k * HID + lane);

#pragma unroll
    for (int i = t; i < GEMM_ROWS * (IN_DIM / 4); i += 256) {
        int r = i >> 4;
        if (row0 + r < n) xs4[i] = X4[row0 * (IN_DIM / 4) + i];
    }
    __syncthreads();

#pragma unroll
    for (int rr = 0; rr < 8; rr++) {
        int rl  = warp * 8 + rr;
        int row = row0 + rl;
        if (row >= n) break;

        const float4* xr = xs4 + rl * (IN_DIM / 4);
        float acc = 0.f;
#pragma unroll
        for (int k4 = 0; k4 < IN_DIM / 4; k4++) {
            float4 x = xr[k4];          // broadcast LDS.128
            acc += x.x * w[k4 * 4 + 0];
            acc += x.y * w[k4 * 4 + 1];
            acc += x.z * w[k4 * 4 + 2];
            acc += x.w * w[k4 * 4 + 3];
        }
        g_h[row * HID + lane] = __float2half(acc);
    }
}

// ---------------------------------------------------------------------------
// 2) norm_h: h[row,:] *= rsqrt(max(degout[row],1)).  uint4 = 8 halfs/thread.
// ---------------------------------------------------------------------------
__global__ void norm_h_kernel(int n) {
    int i = blockIdx.x * blockDim.x + threadIdx.x;   // [0, n*4)
    if (i >= n * (HID / 8)) return;
    int row = i >> 2;                                // 4 chunks of 8 halfs per row
    float nrm = rsqrtf(fmaxf(g_degout[row], 1.f));
    __half2 nh = __float2half2_rn(nrm);
    uint4 raw = reinterpret_cast<uint4*>(g_h)[i];
    __half2* h = reinterpret_cast<__half2*>(&raw);
    h[0] = __hmul2(h[0], nh);
    h[1] = __hmul2(h[1], nh);
    h[2] = __hmul2(h[2], nh);
    h[3] = __hmul2(h[3], nh);
    reinterpret_cast<uint4*>(g_h)[i] = raw;
}

// ---------------------------------------------------------------------------
// 3) edge scatter: out[dst] += h[src].  512-edge tiles, smem-staged indices;
//    8 threads/edge, each gathers 4 halfs (8B), converts, red.add.v4.f32.
// ---------------------------------------------------------------------------
#define TILE 512
__global__ void scatter_kernel(const int* __restrict__ src,
                               const int* __restrict__ dst,
                               float* __restrict__ out, int e) {
    __shared__ int s_src[TILE];
    __shared__ int s_dst[TILE];

    int base = blockIdx.x * TILE;
    int tile_n = min(TILE, e - base);

    for (int i = threadIdx.x; i < tile_n; i += blockDim.x) {
        s_src[i] = src[base + i];
        s_dst[i] = dst[base + i];
    }
    __syncthreads();

    int sub = threadIdx.x >> 3;          // edge slot within pass (0..31)
    int c   = (threadIdx.x & 7) << 2;    // float col offset 0,4,...,28

#pragma unroll 4
    for (int k = 0; k < TILE; k += 32) {
        int el = k + sub;
        if (el >= tile_n) break;
        int s = s_src[el];               // broadcast LDS
        int d = s_dst[el];
        uint2 raw = *reinterpret_cast<const uint2*>(g_h + s * HID + c);
        __half2 h01 = *reinterpret_cast<__half2*>(&raw.x);
        __half2 h23 = *reinterpret_cast<__half2*>(&raw.y);
        float2 f01 = __half22float2(h01);
        float2 f23 = __half22float2(h23);
        float* p = out + d * HID + c;
        asm volatile("red.global.add.v4.f32 [%0], {%1,%2,%3,%4};"
                     :: "l"(p), "f"(f01.x), "f"(f01.y), "f"(f23.x), "f"(f23.y)
                     : "memory");
    }
}

// ---------------------------------------------------------------------------
// 4) out = relu(agg * norm_dst + b), in place, float4-vectorized
// ---------------------------------------------------------------------------
__global__ void fin_kernel(float4* __restrict__ out4,
                           const float* __restrict__ b, int n) {
    int i = blockIdx.x * blockDim.x + threadIdx.x;   // [0, n*8)
    if (i >= n * (HID / 4)) return;
    int row  = i >> 3;
    int col4 = (i & 7) << 2;
    float nrm = rsqrtf(fmaxf(g_degin[row], 1.f));
    float4 v = out4[i];
    v.x = fmaxf(v.x * nrm + b[col4 + 0], 0.f);
    v.y = fmaxf(v.y * nrm + b[col4 + 1], 0.f);
    v.z = fmaxf(v.z * nrm + b[col4 + 2], 0.f);
    v.w = fmaxf(v.w * nrm + b[col4 + 3], 0.f);
    out4[i] = v;
}

// ---------------------------------------------------------------------------
extern "C" void kernel_launch(void* const* d_in, const int* in_sizes, int n_in,
                              void* d_out, int out_size) {
    const float* features = (const float*)d_in[0];   // [N, 64]
    const int*   src      = (const int*)  d_in[1];   // [E]
    const int*   dst      = (const int*)  d_in[2];   // [E]
    const float* W        = (const float*)d_in[3];   // [64, 32]
    const float* b        = (const float*)d_in[4];   // [32]
    float*       out      = (float*)d_out;           // [N, 32]

    int n = in_sizes[0] / IN_DIM;                    // 100000
    int e = in_sizes[1];                             // 1600000

    // 0) zero accumulators via memset nodes
    void* p_degout = nullptr;
    void* p_degin  = nullptr;
    cudaGetSymbolAddress(&p_degout, g_degout);
    cudaGetSymbolAddress(&p_degin,  g_degin);
    cudaMemsetAsync(out, 0, (size_t)n * HID * sizeof(float), 0);
    cudaMemsetAsync(p_degout, 0, (size_t)n * sizeof(float), 0);
    cudaMemsetAsync(p_degin,  0, (size_t)n * sizeof(float), 0);

    // 1) fused gemm_raw + degrees (parity-interleaved block roles)
    int gemm_blocks = (n + GEMM_ROWS - 1) / GEMM_ROWS;          // 1563
    int deg_blocks  = ((e >> 2) + 255) / 256;                   // 1563
    int total_blocks = 2 * (gemm_blocks > deg_blocks ? gemm_blocks : deg_blocks);
    fused_gemm_deg_kernel<<<total_blocks, 256>>>(
        (const float4*)features, W, (const int4*)src, (const int4*)dst, n, e);

    // 2) apply norm_src to h
    norm_h_kernel<<<(n * (HID / 8) + 255) / 256, 256>>>(n);

    // 3) scatter-add over edges
    scatter_kernel<<<(e + TILE - 1) / TILE, 256>>>(src, dst, out, e);

    // 4) finalize
    fin_kernel<<<(n * (HID / 4) + 255) / 256, 256>>>((float4*)out, b, n);
}